// round 11
// baseline (speedup 1.0000x reference)
#include <cuda_runtime.h>
#include <cuda_fp16.h>

#define NCTA 128
#define NTHR 512
#define Tn   512
#define TPn  544

// SMEM byte map (A staging removed; slots are dedicated now)
#define SM_B      0                     // 96KB weight fragments (hi/lo planes)
#define SM_SLOT0  98304                 // 32KB reduce slot (kp1)
#define SM_SLOT1  (SM_SLOT0 + 32768)    // kp2
#define SM_SLOT2  (SM_SLOT0 + 65536)    // kp3
#define SM_Z      (SM_SLOT0 + 98304)    // zbuf 32*257*4 = 32896 B
#define SM_MISC   (SM_Z + 32896)
#define SM_TOTAL  (SM_MISC + 256)

#define BOFFU(m,q,p,nt,L) ((((((m)*32+(q))*2+(p))*2+(nt))*32+(L))*2)

__device__ __align__(16) unsigned g_h1[2][131072];  // fp16 planes, A-frag order
__device__ __align__(16) unsigned g_h2[2][131072];
__device__ float    g_opart[256 * NCTA];            // [b][cta]
__device__ float    g_out[TPn * 256];               // [t][b], raw (no bl)
__device__ unsigned g_flags[NCTA];

__device__ __forceinline__ float sigf(float x) { return 1.f / (1.f + __expf(-x)); }

__device__ __forceinline__ void mma16816(float* c, const unsigned* a, const unsigned* b) {
  asm volatile(
      "mma.sync.aligned.m16n8k16.row.col.f32.f16.f16.f32 "
      "{%0,%1,%2,%3},{%4,%5,%6,%7},{%8,%9},{%0,%1,%2,%3};\n"
      : "+f"(c[0]), "+f"(c[1]), "+f"(c[2]), "+f"(c[3])
      : "r"(a[0]), "r"(a[1]), "r"(a[2]), "r"(a[3]), "r"(b[0]), "r"(b[1]));
}

__device__ __forceinline__ uint4 ldcg128(const uint4* p) {
  uint4 v;
  asm volatile("ld.global.cg.v4.u32 {%0,%1,%2,%3}, [%4];"
               : "=r"(v.x), "=r"(v.y), "=r"(v.z), "=r"(v.w) : "l"(p));
  return v;
}

__device__ __forceinline__ void grid_barrier(unsigned& gen) {
  __threadfence();
  __syncthreads();
  ++gen;
  if (threadIdx.x == 0)
    asm volatile("st.release.gpu.u32 [%0], %1;" :: "l"(&g_flags[blockIdx.x]), "r"(gen));
  if (threadIdx.x < NCTA) {
    unsigned v;
    do {
      asm volatile("ld.acquire.gpu.u32 %0, [%1];" : "=r"(v) : "l"(&g_flags[threadIdx.x]));
    } while ((int)(v - gen) < 0);
  }
  __syncthreads();
}

// write h[b][u0..u0+3] as hi/lo fp16 planes in A-fragment order
__device__ __forceinline__ void h_write(unsigned* gb, int b, int cta, const float* hv) {
  int q = cta >> 2, kcb = (cta & 3) * 4, mtg = b >> 4;
  __half hh[4], hl[4];
#pragma unroll
  for (int u = 0; u < 4; ++u) {
    hh[u] = __float2half_rn(hv[u]);
    hl[u] = __float2half_rn(hv[u] - __half2float(hh[u]));
  }
#pragma unroll
  for (int j = 0; j < 2; ++j) {
    int kc0 = kcb + 2 * j;
    int L   = ((b & 7) << 2) | ((kc0 & 7) >> 1);
    int rg  = ((b >> 3) & 1) | ((kc0 >> 3) << 1);
    __half2 vh = __halves2half2(hh[2 * j], hh[2 * j + 1]);
    __half2 vl = __halves2half2(hl[2 * j], hl[2 * j + 1]);
    gb[((q * 2 + 0) * 16 + mtg) * 128 + L * 4 + rg] = *reinterpret_cast<unsigned*>(&vh);
    gb[((q * 2 + 1) * 16 + mtg) * 128 + L * 4 + rg] = *reinterpret_cast<unsigned*>(&vl);
  }
}

__global__ void __launch_bounds__(NTHR, 1) sine_rnn_kernel(
    const float* __restrict__ seq,
    const float* __restrict__ Wx1, const float* __restrict__ bx1,
    const float* __restrict__ Wh1, const float* __restrict__ bh1,
    const float* __restrict__ Wx2, const float* __restrict__ bx2,
    const float* __restrict__ Wh2, const float* __restrict__ bh2,
    const float* __restrict__ Wl,  const float* __restrict__ bl,
    float* __restrict__ out)
{
  extern __shared__ char smem[];
  const int tid  = threadIdx.x;
  const int lane = tid & 31;
  const int warp = tid >> 5;
  const int kp   = warp & 3;   // K-part (128 k each)
  const int mp   = warp >> 2;  // M-part (64 batches each)
  const int cta  = blockIdx.x;
  const int u0   = cta * 4;
  const float bl0 = __ldg(&bl[0]);

  float* misc = reinterpret_cast<float*>(smem + SM_MISC);
  // ---- init: weight fragments (hi/lo) + misc ----
  for (int idx = tid; idx < 3 * 512 * 16; idx += NTHR) {
    int m = idx >> 13, r = idx & 8191, k = r >> 4, gc = r & 15;
    int col = u0 + (gc & 3) + ((gc >> 2) << 9);
    const float* Wm = (m == 0) ? Wh2 : ((m == 1) ? Wx2 : Wh1);
    float v = Wm[k * 2048 + col];
    __half hi = __float2half_rn(v);
    __half lo = __float2half_rn(v - __half2float(hi));
    int q = k >> 4, kc = k & 15, nt = gc >> 3, n = gc & 7;
    int L = (n << 2) | ((kc & 7) >> 1), rg = kc >> 3, hf = kc & 1;
    __half* hp = reinterpret_cast<__half*>(smem + SM_B);
    hp[(BOFFU(m, q, 0, nt, L) + rg) * 2 + hf] = hi;
    hp[(BOFFU(m, q, 1, nt, L) + rg) * 2 + hf] = lo;
  }
  if (tid < 16) {
    int gc = tid;
    int col = u0 + (gc & 3) + ((gc >> 2) << 9);
    misc[gc]      = bx1[col] + bh1[col];
    misc[16 + gc] = bx2[col] + bh2[col];
    misc[32 + gc] = Wx1[col];
  }
  if (tid < 4) misc[48 + tid] = Wl[u0 + tid];
  __syncthreads();

  float c1s[4] = {0, 0, 0, 0}, c2s[4] = {0, 0, 0, 0};

  // h1(0) from x(0); zero slice of g_h2[1]
  if (tid < 256) {
    int b = tid;
    float x0 = __ldg(&seq[b * Tn]);
    float hv[4];
#pragma unroll
    for (int u = 0; u < 4; ++u) {
      float zi = fmaf(x0, misc[32 + u],      misc[u]);
      float zo = fmaf(x0, misc[32 + 8 + u],  misc[8 + u]);
      float zg = fmaf(x0, misc[32 + 12 + u], misc[12 + u]);
      float c = sigf(zi) * tanhf(zg);
      c1s[u] = c;
      hv[u] = sigf(zo) * tanhf(c);
    }
    h_write(g_h1[0], b, cta, hv);
  }
  for (int i = tid; i < 1024; i += NTHR) g_h2[1][cta * 1024 + i] = 0u;

  unsigned gen;
  asm volatile("ld.acquire.gpu.u32 %0, [%1];" : "=r"(gen) : "l"(&g_flags[cta]));
  grid_barrier(gen);

  for (int t = 0; t < TPn; ++t) {
    const bool pred = (t >= Tn - 1);

    const unsigned* src_h2 = g_h2[(t ^ 1) & 1];
    const unsigned* src_h1 = g_h1[t & 1];

    // main-phase o(t-1): owner reduces partials
    if (t >= 1 && t <= Tn - 1 && warp < 2) {
      int ob = 2 * cta + warp;
      float4 v = __ldcg(reinterpret_cast<const float4*>(g_opart + ob * NCTA) + lane);
      float p = v.x + v.y + v.z + v.w;
#pragma unroll
      for (int off = 16; off; off >>= 1) p += __shfl_xor_sync(0xffffffffu, p, off);
      if (lane == 0) g_out[(t - 1) * 256 + ob] = p;
    }

    float z2a[4][2][4], z1a[4][2][4];
#pragma unroll
    for (int i = 0; i < 32; ++i) {
      reinterpret_cast<float*>(z2a)[i] = 0.f;
      reinterpret_cast<float*>(z1a)[i] = 0.f;
    }

    // ---- A fragments straight from L2 (h stored in A-frag order) ----
    auto loadA = [&](int cc, uint4* a) {
      int phase = cc >> 3, rr = cc & 7;
      int q = kp * 8 + rr;
      const uint4* g = reinterpret_cast<const uint4*>(
                           (phase < 2) ? src_h2 : src_h1) +
                       (q * 2 + (phase & 1)) * 512 + mp * 128 + lane;
#pragma unroll
      for (int mt = 0; mt < 4; ++mt) a[mt] = ldcg128(g + mt * 32);
    };
    auto computeC = [&](int cc, const uint4* a) {
      int phase = cc >> 3, rr = cc & 7;
      int q = kp * 8 + rr;
      auto dob = [&](int m, int p, float (*acc)[2][4]) {
#pragma unroll
        for (int nt = 0; nt < 2; ++nt) {
          uint2 bv = *reinterpret_cast<const uint2*>(
              smem + SM_B + BOFFU(m, q, p, nt, lane) * 4);
#pragma unroll
          for (int mt = 0; mt < 4; ++mt)
            mma16816(acc[mt][nt], reinterpret_cast<const unsigned*>(&a[mt]),
                     reinterpret_cast<const unsigned*>(&bv));
        }
      };
      if (phase == 0)      { dob(0, 0, z2a); dob(0, 1, z2a); }
      else if (phase == 1) { dob(0, 0, z2a); }
      else if (phase == 2) { dob(1, 0, z2a); dob(1, 1, z2a);
                             dob(2, 0, z1a); dob(2, 1, z1a); }
      else                 { dob(1, 0, z2a); dob(2, 0, z1a); }
    };

    // 32 chunks, software-pipelined depth 1, fully unrolled
    {
      uint4 aA[4], aB[4];
      loadA(0, aA);
#pragma unroll
      for (int cc = 0; cc < 32; cc += 2) {
        loadA(cc + 1, aB);
        computeC(cc, aA);
        if (cc + 2 < 32) loadA(cc + 2, aA);
        computeC(cc + 1, aB);
      }
    }
    __syncthreads();

    // ---- reduce K-partials: kp1->slot0, kp2->slot1, kp3->slot2 ----
    {
      float* slot = nullptr;
      if (kp == 1) slot = reinterpret_cast<float*>(smem + SM_SLOT0) + (mp * 32 + lane) * 64;
      if (kp == 2) slot = reinterpret_cast<float*>(smem + SM_SLOT1) + (mp * 32 + lane) * 64;
      if (kp == 3) slot = reinterpret_cast<float*>(smem + SM_SLOT2) + (mp * 32 + lane) * 64;
      if (slot) {
#pragma unroll
        for (int i = 0; i < 32; ++i) {
          slot[i]      = reinterpret_cast<float*>(z2a)[i];
          slot[32 + i] = reinterpret_cast<float*>(z1a)[i];
        }
      }
    }
    __syncthreads();
    if (kp == 0) {
      const float* s1 = reinterpret_cast<float*>(smem + SM_SLOT0) + (mp * 32 + lane) * 64;
      const float* s2 = reinterpret_cast<float*>(smem + SM_SLOT1) + (mp * 32 + lane) * 64;
      const float* s3 = reinterpret_cast<float*>(smem + SM_SLOT2) + (mp * 32 + lane) * 64;
#pragma unroll
      for (int i = 0; i < 32; ++i) {
        reinterpret_cast<float*>(z2a)[i] += s1[i] + s2[i] + s3[i];
        reinterpret_cast<float*>(z1a)[i] += s1[32 + i] + s2[32 + i] + s3[32 + i];
      }
      float* zb = reinterpret_cast<float*>(smem + SM_Z);
#pragma unroll
      for (int mt = 0; mt < 4; ++mt)
#pragma unroll
        for (int nt = 0; nt < 2; ++nt)
#pragma unroll
          for (int ci = 0; ci < 4; ++ci) {
            int b  = mp * 64 + mt * 16 + (lane >> 2) + 8 * (ci >> 1);
            int gc = nt * 8 + (lane & 3) * 2 + (ci & 1);
            zb[gc * 257 + b]        = z2a[mt][nt][ci];
            zb[(16 + gc) * 257 + b] = z1a[mt][nt][ci];
          }
    }
    __syncthreads();

    // ---- epilogue layer 2 -> h2(t), opart ----
    const float* zb = reinterpret_cast<const float*>(smem + SM_Z);
    if (tid < 256) {
      int b = tid;
      float hv[4], op = 0.f;
#pragma unroll
      for (int u = 0; u < 4; ++u) {
        float zi = zb[(u) * 257 + b]      + misc[16 + u];
        float zf = zb[(4 + u) * 257 + b]  + misc[16 + 4 + u];
        float zo = zb[(8 + u) * 257 + b]  + misc[16 + 8 + u];
        float zg = zb[(12 + u) * 257 + b] + misc[16 + 12 + u];
        float c = sigf(zf) * c2s[u] + sigf(zi) * tanhf(zg);
        c2s[u] = c;
        hv[u] = sigf(zo) * tanhf(c);
        op = fmaf(hv[u], misc[48 + u], op);
      }
      h_write(g_h2[t & 1], b, cta, hv);
      g_opart[b * NCTA + cta] = op;
    }

    // ---- next input ----
    float xnext = 0.f;
    if (!pred) {
      if (tid < 256) xnext = __ldg(&seq[tid * Tn + (t + 1)]);
    } else {
      grid_barrier(gen);
      if (warp < 2) {
        int ob = 2 * cta + warp;
        float4 v = __ldcg(reinterpret_cast<const float4*>(g_opart + ob * NCTA) + lane);
        float p = v.x + v.y + v.z + v.w;
#pragma unroll
        for (int off = 16; off; off >>= 1) p += __shfl_xor_sync(0xffffffffu, p, off);
        if (lane == 0) g_out[t * 256 + ob] = p;
      }
      grid_barrier(gen);
      if (tid < 256) xnext = __ldcg(&g_out[t * 256 + tid]) + bl0;
    }

    // ---- epilogue layer 1 -> h1(t+1) ----
    if (tid < 256) {
      int b = tid;
      float hv[4];
#pragma unroll
      for (int u = 0; u < 4; ++u) {
        float zi = fmaf(xnext, misc[32 + u],      zb[(16 + u) * 257 + b]      + misc[u]);
        float zf = fmaf(xnext, misc[32 + 4 + u],  zb[(16 + 4 + u) * 257 + b]  + misc[4 + u]);
        float zo = fmaf(xnext, misc[32 + 8 + u],  zb[(16 + 8 + u) * 257 + b]  + misc[8 + u]);
        float zg = fmaf(xnext, misc[32 + 12 + u], zb[(16 + 12 + u) * 257 + b] + misc[12 + u]);
        float c = sigf(zf) * c1s[u] + sigf(zi) * tanhf(zg);
        c1s[u] = c;
        hv[u] = sigf(zo) * tanhf(c);
      }
      h_write(g_h1[(t + 1) & 1], b, cta, hv);
    }
    grid_barrier(gen);
  }

  // out[b][tp] = o + bl
  for (int idx = cta * NTHR + tid; idx < TPn * 256; idx += NCTA * NTHR) {
    int b = idx / TPn, tp = idx - b * TPn;
    out[idx] = __ldcg(&g_out[tp * 256 + b]) + bl0;
  }
}

extern "C" void kernel_launch(void* const* d_in, const int* in_sizes, int n_in,
                              void* d_out, int out_size) {
  (void)in_sizes; (void)n_in; (void)out_size;
  const float* seq = (const float*)d_in[0];
  const float* Wx1 = (const float*)d_in[2];
  const float* bx1 = (const float*)d_in[3];
  const float* Wh1 = (const float*)d_in[4];
  const float* bh1 = (const float*)d_in[5];
  const float* Wx2 = (const float*)d_in[6];
  const float* bx2 = (const float*)d_in[7];
  const float* Wh2 = (const float*)d_in[8];
  const float* bh2 = (const float*)d_in[9];
  const float* Wl  = (const float*)d_in[10];
  const float* bl  = (const float*)d_in[11];

  cudaFuncSetAttribute(sine_rnn_kernel,
                       cudaFuncAttributeMaxDynamicSharedMemorySize, SM_TOTAL);
  sine_rnn_kernel<<<NCTA, NTHR, SM_TOTAL>>>(
      seq, Wx1, bx1, Wh1, bh1, Wx2, bx2, Wh2, bh2, Wl, bl, (float*)d_out);
}

// round 12
// speedup vs baseline: 1.9663x; 1.9663x over previous
#include <cuda_runtime.h>
#include <cuda_fp16.h>

#define NCTA 128
#define NTHR 512
#define Tn   512
#define TPn  544

// SMEM byte map
#define SM_B      0                 // 96KB weight fragments, uint4 = [hi0,hi1,lo0,lo1]
#define SM_Z      98304             // zbuf 32*257*4 = 32896 B
#define SM_MISC   (SM_Z + 32896)
#define SM_TOTAL  (SM_MISC + 256)

// uint4 index for B fragment block (m matrix, q k-chunk, nt n-tile, L lane)
#define BOFF4(m,q,nt,L) (((((m)*32+(q))*2+(nt))*32+(L)))

__device__ __align__(16) unsigned g_h1[2][131072];  // fp16 planes, A-frag order
__device__ __align__(16) unsigned g_h2[2][131072];
__device__ float    g_opart[256 * NCTA];            // [b][cta]
__device__ float    g_out[TPn * 256];               // [t][b], raw (no bl)
__device__ unsigned g_flags[NCTA];

__device__ __forceinline__ float sigf(float x) { return 1.f / (1.f + __expf(-x)); }

__device__ __forceinline__ void mma16816(float* c, const uint4& a,
                                         unsigned b0, unsigned b1) {
  asm volatile(
      "mma.sync.aligned.m16n8k16.row.col.f32.f16.f16.f32 "
      "{%0,%1,%2,%3},{%4,%5,%6,%7},{%8,%9},{%0,%1,%2,%3};\n"
      : "+f"(c[0]), "+f"(c[1]), "+f"(c[2]), "+f"(c[3])
      : "r"(a.x), "r"(a.y), "r"(a.z), "r"(a.w), "r"(b0), "r"(b1));
}

__device__ __forceinline__ uint4 ldcg128(const uint4* p) {
  uint4 v;
  asm volatile("ld.global.cg.v4.u32 {%0,%1,%2,%3}, [%4];"
               : "=r"(v.x), "=r"(v.y), "=r"(v.z), "=r"(v.w) : "l"(p));
  return v;
}

__device__ __forceinline__ void grid_barrier(unsigned& gen) {
  __threadfence();
  __syncthreads();
  ++gen;
  if (threadIdx.x == 0)
    asm volatile("st.release.gpu.u32 [%0], %1;" :: "l"(&g_flags[blockIdx.x]), "r"(gen));
  if (threadIdx.x < NCTA) {
    unsigned v;
    do {
      asm volatile("ld.acquire.gpu.u32 %0, [%1];" : "=r"(v) : "l"(&g_flags[threadIdx.x]));
    } while ((int)(v - gen) < 0);
  }
  __syncthreads();
}

// write h[b][u0..u0+3] as hi/lo fp16 planes in A-fragment order
__device__ __forceinline__ void h_write(unsigned* gb, int b, int cta, const float* hv) {
  int q = cta >> 2, kcb = (cta & 3) * 4, mtg = b >> 4;
  __half hh[4], hl[4];
#pragma unroll
  for (int u = 0; u < 4; ++u) {
    hh[u] = __float2half_rn(hv[u]);
    hl[u] = __float2half_rn(hv[u] - __half2float(hh[u]));
  }
#pragma unroll
  for (int j = 0; j < 2; ++j) {
    int kc0 = kcb + 2 * j;
    int L   = ((b & 7) << 2) | ((kc0 & 7) >> 1);
    int rg  = ((b >> 3) & 1) | ((kc0 >> 3) << 1);
    __half2 vh = __halves2half2(hh[2 * j], hh[2 * j + 1]);
    __half2 vl = __halves2half2(hl[2 * j], hl[2 * j + 1]);
    gb[((q * 2 + 0) * 16 + mtg) * 128 + L * 4 + rg] = *reinterpret_cast<unsigned*>(&vh);
    gb[((q * 2 + 1) * 16 + mtg) * 128 + L * 4 + rg] = *reinterpret_cast<unsigned*>(&vl);
  }
}

__global__ void __launch_bounds__(NTHR, 1) sine_rnn_kernel(
    const float* __restrict__ seq,
    const float* __restrict__ Wx1, const float* __restrict__ bx1,
    const float* __restrict__ Wh1, const float* __restrict__ bh1,
    const float* __restrict__ Wx2, const float* __restrict__ bx2,
    const float* __restrict__ Wh2, const float* __restrict__ bh2,
    const float* __restrict__ Wl,  const float* __restrict__ bl,
    float* __restrict__ out)
{
  extern __shared__ char smem[];
  const int tid  = threadIdx.x;
  const int lane = tid & 31;
  const int warp = tid >> 5;
  const int mp   = warp;       // M-part: batches [mp*16, mp*16+16), full K
  const int cta  = blockIdx.x;
  const int u0   = cta * 4;
  const float bl0 = __ldg(&bl[0]);

  float* misc = reinterpret_cast<float*>(smem + SM_MISC);
  // ---- init: weight fragments (hi|lo packed per uint4) + misc ----
  for (int idx = tid; idx < 3 * 512 * 16; idx += NTHR) {
    int m = idx >> 13, r = idx & 8191, k = r >> 4, gc = r & 15;
    int col = u0 + (gc & 3) + ((gc >> 2) << 9);
    const float* Wm = (m == 0) ? Wh2 : ((m == 1) ? Wx2 : Wh1);
    float v = Wm[k * 2048 + col];
    __half hi = __float2half_rn(v);
    __half lo = __float2half_rn(v - __half2float(hi));
    int q = k >> 4, kc = k & 15, nt = gc >> 3, n = gc & 7;
    int L = (n << 2) | ((kc & 7) >> 1), rg = kc >> 3, hf = kc & 1;
    __half* hp = reinterpret_cast<__half*>(smem + SM_B);
    int base = BOFF4(m, q, nt, L) * 4;  // uint index of the uint4
    hp[(base + 0 * 2 + rg) * 2 + hf] = hi;   // hi plane -> uints 0,1
    hp[(base + 1 * 2 + rg) * 2 + hf] = lo;   // lo plane -> uints 2,3
  }
  if (tid < 16) {
    int gc = tid;
    int col = u0 + (gc & 3) + ((gc >> 2) << 9);
    misc[gc]      = bx1[col] + bh1[col];
    misc[16 + gc] = bx2[col] + bh2[col];
    misc[32 + gc] = Wx1[col];
  }
  if (tid < 4) misc[48 + tid] = Wl[u0 + tid];
  __syncthreads();

  float c1s[4] = {0, 0, 0, 0}, c2s[4] = {0, 0, 0, 0};

  // h1(0) from x(0); zero slice of g_h2[1]
  if (tid < 256) {
    int b = tid;
    float x0 = __ldg(&seq[b * Tn]);
    float hv[4];
#pragma unroll
    for (int u = 0; u < 4; ++u) {
      float zi = fmaf(x0, misc[32 + u],      misc[u]);
      float zo = fmaf(x0, misc[32 + 8 + u],  misc[8 + u]);
      float zg = fmaf(x0, misc[32 + 12 + u], misc[12 + u]);
      float c = sigf(zi) * tanhf(zg);
      c1s[u] = c;
      hv[u] = sigf(zo) * tanhf(c);
    }
    h_write(g_h1[0], b, cta, hv);
  }
  for (int i = tid; i < 1024; i += NTHR) g_h2[1][cta * 1024 + i] = 0u;

  unsigned gen;
  asm volatile("ld.acquire.gpu.u32 %0, [%1];" : "=r"(gen) : "l"(&g_flags[cta]));
  grid_barrier(gen);

  const uint4* Bsm = reinterpret_cast<const uint4*>(smem + SM_B);

  for (int t = 0; t < TPn; ++t) {
    const bool pred = (t >= Tn - 1);

    const uint4* pH2 = reinterpret_cast<const uint4*>(g_h2[(t ^ 1) & 1]);
    const uint4* pH1 = reinterpret_cast<const uint4*>(g_h1[t & 1]);

    // main-phase o(t-1): owner reduces partials
    if (t >= 1 && t <= Tn - 1 && warp < 2) {
      int ob = 2 * cta + warp;
      float4 v = __ldcg(reinterpret_cast<const float4*>(g_opart + ob * NCTA) + lane);
      float p = v.x + v.y + v.z + v.w;
#pragma unroll
      for (int off = 16; off; off >>= 1) p += __shfl_xor_sync(0xffffffffu, p, off);
      if (lane == 0) g_out[(t - 1) * 256 + ob] = p;
    }

    float z2a[2][4], z1a[2][4];
#pragma unroll
    for (int i = 0; i < 8; ++i) {
      reinterpret_cast<float*>(z2a)[i] = 0.f;
      reinterpret_cast<float*>(z1a)[i] = 0.f;
    }

    // chunk cc = q*4 + ph ; ph: 0=h2hi, 1=h2lo, 2=h1hi, 3=h1lo
    auto loadA = [&](int cc) -> uint4 {
      int q = cc >> 2, ph = cc & 3;
      const uint4* base = (ph < 2) ? pH2 : pH1;
      return ldcg128(base + ((q * 2 + (ph & 1)) * 16 + mp) * 32 + lane);
    };

    uint4 Bq[6];
    auto loadBq = [&](int q) {
#pragma unroll
      for (int m = 0; m < 3; ++m)
#pragma unroll
        for (int nt = 0; nt < 2; ++nt)
          Bq[m * 2 + nt] = Bsm[BOFF4(m, q, nt, lane)];
    };

    auto compute = [&](int cc, const uint4& a) {
      int ph = cc & 3;
      if (ph == 0) {
#pragma unroll
        for (int nt = 0; nt < 2; ++nt) {
          mma16816(z2a[nt], a, Bq[nt].x, Bq[nt].y);
          mma16816(z2a[nt], a, Bq[nt].z, Bq[nt].w);
        }
      } else if (ph == 1) {
#pragma unroll
        for (int nt = 0; nt < 2; ++nt)
          mma16816(z2a[nt], a, Bq[nt].x, Bq[nt].y);
      } else if (ph == 2) {
#pragma unroll
        for (int nt = 0; nt < 2; ++nt) {
          mma16816(z2a[nt], a, Bq[2 + nt].x, Bq[2 + nt].y);
          mma16816(z2a[nt], a, Bq[2 + nt].z, Bq[2 + nt].w);
          mma16816(z1a[nt], a, Bq[4 + nt].x, Bq[4 + nt].y);
          mma16816(z1a[nt], a, Bq[4 + nt].z, Bq[4 + nt].w);
        }
      } else {
#pragma unroll
        for (int nt = 0; nt < 2; ++nt) {
          mma16816(z2a[nt], a, Bq[2 + nt].x, Bq[2 + nt].y);
          mma16816(z1a[nt], a, Bq[4 + nt].x, Bq[4 + nt].y);
        }
      }
    };

    // 128 tiny chunks, 8-deep register ring of A fragments
    {
      uint4 ar[8];
#pragma unroll
      for (int i = 0; i < 8; ++i) ar[i] = loadA(i);
#pragma unroll 8
      for (int cc = 0; cc < 120; ++cc) {
        if ((cc & 3) == 0) loadBq(cc >> 2);
        compute(cc, ar[cc & 7]);
        ar[cc & 7] = loadA(cc + 8);
      }
#pragma unroll
      for (int cc = 120; cc < 128; ++cc) {
        if ((cc & 3) == 0) loadBq(cc >> 2);
        compute(cc, ar[cc & 7]);
      }
    }

    // ---- each warp writes its z tiles straight to zbuf (no K-reduce) ----
    {
      float* zb = reinterpret_cast<float*>(smem + SM_Z);
#pragma unroll
      for (int nt = 0; nt < 2; ++nt)
#pragma unroll
        for (int ci = 0; ci < 4; ++ci) {
          int b  = mp * 16 + (lane >> 2) + 8 * (ci >> 1);
          int gc = nt * 8 + (lane & 3) * 2 + (ci & 1);
          zb[gc * 257 + b]        = z2a[nt][ci];
          zb[(16 + gc) * 257 + b] = z1a[nt][ci];
        }
    }
    __syncthreads();

    // ---- epilogue layer 2 -> h2(t), opart ----
    const float* zb = reinterpret_cast<const float*>(smem + SM_Z);
    if (tid < 256) {
      int b = tid;
      float hv[4], op = 0.f;
#pragma unroll
      for (int u = 0; u < 4; ++u) {
        float zi = zb[(u) * 257 + b]      + misc[16 + u];
        float zf = zb[(4 + u) * 257 + b]  + misc[16 + 4 + u];
        float zo = zb[(8 + u) * 257 + b]  + misc[16 + 8 + u];
        float zg = zb[(12 + u) * 257 + b] + misc[16 + 12 + u];
        float c = sigf(zf) * c2s[u] + sigf(zi) * tanhf(zg);
        c2s[u] = c;
        hv[u] = sigf(zo) * tanhf(c);
        op = fmaf(hv[u], misc[48 + u], op);
      }
      h_write(g_h2[t & 1], b, cta, hv);
      g_opart[b * NCTA + cta] = op;
    }

    // ---- next input ----
    float xnext = 0.f;
    if (!pred) {
      if (tid < 256) xnext = __ldg(&seq[tid * Tn + (t + 1)]);
    } else {
      grid_barrier(gen);
      if (warp < 2) {
        int ob = 2 * cta + warp;
        float4 v = __ldcg(reinterpret_cast<const float4*>(g_opart + ob * NCTA) + lane);
        float p = v.x + v.y + v.z + v.w;
#pragma unroll
        for (int off = 16; off; off >>= 1) p += __shfl_xor_sync(0xffffffffu, p, off);
        if (lane == 0) g_out[t * 256 + ob] = p;
      }
      grid_barrier(gen);
      if (tid < 256) xnext = __ldcg(&g_out[t * 256 + tid]) + bl0;
    }

    // ---- epilogue layer 1 -> h1(t+1) ----
    if (tid < 256) {
      int b = tid;
      float hv[4];
#pragma unroll
      for (int u = 0; u < 4; ++u) {
        float zi = fmaf(xnext, misc[32 + u],      zb[(16 + u) * 257 + b]      + misc[u]);
        float zf = fmaf(xnext, misc[32 + 4 + u],  zb[(16 + 4 + u) * 257 + b]  + misc[4 + u]);
        float zo = fmaf(xnext, misc[32 + 8 + u],  zb[(16 + 8 + u) * 257 + b]  + misc[8 + u]);
        float zg = fmaf(xnext, misc[32 + 12 + u], zb[(16 + 12 + u) * 257 + b] + misc[12 + u]);
        float c = sigf(zf) * c1s[u] + sigf(zi) * tanhf(zg);
        c1s[u] = c;
        hv[u] = sigf(zo) * tanhf(c);
      }
      h_write(g_h1[(t + 1) & 1], b, cta, hv);
    }
    grid_barrier(gen);
  }

  // out[b][tp] = o + bl
  for (int idx = cta * NTHR + tid; idx < TPn * 256; idx += NCTA * NTHR) {
    int b = idx / TPn, tp = idx - b * TPn;
    out[idx] = __ldcg(&g_out[tp * 256 + b]) + bl0;
  }
}

extern "C" void kernel_launch(void* const* d_in, const int* in_sizes, int n_in,
                              void* d_out, int out_size) {
  (void)in_sizes; (void)n_in; (void)out_size;
  const float* seq = (const float*)d_in[0];
  const float* Wx1 = (const float*)d_in[2];
  const float* bx1 = (const float*)d_in[3];
  const float* Wh1 = (const float*)d_in[4];
  const float* bh1 = (const float*)d_in[5];
  const float* Wx2 = (const float*)d_in[6];
  const float* bx2 = (const float*)d_in[7];
  const float* Wh2 = (const float*)d_in[8];
  const float* bh2 = (const float*)d_in[9];
  const float* Wl  = (const float*)d_in[10];
  const float* bl  = (const float*)d_in[11];

  cudaFuncSetAttribute(sine_rnn_kernel,
                       cudaFuncAttributeMaxDynamicSharedMemorySize, SM_TOTAL);
  sine_rnn_kernel<<<NCTA, NTHR, SM_TOTAL>>>(
      seq, Wx1, bx1, Wh1, bh1, Wx2, bx2, Wh2, bh2, Wl, bl, (float*)d_out);
}

// round 13
// speedup vs baseline: 2.0630x; 1.0492x over previous
#include <cuda_runtime.h>
#include <cuda_fp16.h>

#define NCTA 128
#define NTHR 512
#define Tn   512
#define TPn  544

// SMEM byte map
#define SM_B      0                 // 96KB weight fragments, uint4 = [hi0,hi1,lo0,lo1]
#define SM_Z      98304             // zbuf 32*257*4 = 32896 B
#define SM_MISC   (SM_Z + 32896)
#define SM_TOTAL  (SM_MISC + 256)

// uint4 index for B fragment block (m matrix, q k-chunk, nt n-tile, L lane)
#define BOFF4(m,q,nt,L) (((((m)*32+(q))*2+(nt))*32+(L)))

__device__ __align__(16) unsigned g_h1[2][131072];  // fp16 planes, A-frag order
__device__ __align__(16) unsigned g_h2[2][131072];
__device__ float    g_opart[256 * NCTA];            // [b][cta]
__device__ float    g_out[TPn * 256];               // [t][b], raw (no bl)
__device__ unsigned g_flags[NCTA];

__device__ __forceinline__ float sigf(float x) { return 1.f / (1.f + __expf(-x)); }

__device__ __forceinline__ void mma16816(float* c, const uint4& a,
                                         unsigned b0, unsigned b1) {
  asm volatile(
      "mma.sync.aligned.m16n8k16.row.col.f32.f16.f16.f32 "
      "{%0,%1,%2,%3},{%4,%5,%6,%7},{%8,%9},{%0,%1,%2,%3};\n"
      : "+f"(c[0]), "+f"(c[1]), "+f"(c[2]), "+f"(c[3])
      : "r"(a.x), "r"(a.y), "r"(a.z), "r"(a.w), "r"(b0), "r"(b1));
}

__device__ __forceinline__ uint4 ldcg128(const uint4* p) {
  uint4 v;
  asm volatile("ld.global.cg.v4.u32 {%0,%1,%2,%3}, [%4];"
               : "=r"(v.x), "=r"(v.y), "=r"(v.z), "=r"(v.w) : "l"(p));
  return v;
}

__device__ __forceinline__ void grid_barrier(unsigned& gen) {
  __threadfence();
  __syncthreads();
  ++gen;
  if (threadIdx.x == 0)
    asm volatile("st.release.gpu.u32 [%0], %1;" :: "l"(&g_flags[blockIdx.x]), "r"(gen));
  if (threadIdx.x < NCTA) {
    unsigned v;
    do {
      asm volatile("ld.acquire.gpu.u32 %0, [%1];" : "=r"(v) : "l"(&g_flags[threadIdx.x]));
    } while ((int)(v - gen) < 0);
  }
  __syncthreads();
}

// write h[b][u0..u0+3] as hi/lo fp16 planes in A-fragment order
__device__ __forceinline__ void h_write(unsigned* gb, int b, int cta, const float* hv) {
  int q = cta >> 2, kcb = (cta & 3) * 4, mtg = b >> 4;
  __half hh[4], hl[4];
#pragma unroll
  for (int u = 0; u < 4; ++u) {
    hh[u] = __float2half_rn(hv[u]);
    hl[u] = __float2half_rn(hv[u] - __half2float(hh[u]));
  }
#pragma unroll
  for (int j = 0; j < 2; ++j) {
    int kc0 = kcb + 2 * j;
    int L   = ((b & 7) << 2) | ((kc0 & 7) >> 1);
    int rg  = ((b >> 3) & 1) | ((kc0 >> 3) << 1);
    __half2 vh = __halves2half2(hh[2 * j], hh[2 * j + 1]);
    __half2 vl = __halves2half2(hl[2 * j], hl[2 * j + 1]);
    gb[((q * 2 + 0) * 16 + mtg) * 128 + L * 4 + rg] = *reinterpret_cast<unsigned*>(&vh);
    gb[((q * 2 + 1) * 16 + mtg) * 128 + L * 4 + rg] = *reinterpret_cast<unsigned*>(&vl);
  }
}

__global__ void __launch_bounds__(NTHR, 1) sine_rnn_kernel(
    const float* __restrict__ seq,
    const float* __restrict__ Wx1, const float* __restrict__ bx1,
    const float* __restrict__ Wh1, const float* __restrict__ bh1,
    const float* __restrict__ Wx2, const float* __restrict__ bx2,
    const float* __restrict__ Wh2, const float* __restrict__ bh2,
    const float* __restrict__ Wl,  const float* __restrict__ bl,
    float* __restrict__ out)
{
  extern __shared__ char smem[];
  const int tid  = threadIdx.x;
  const int lane = tid & 31;
  const int warp = tid >> 5;
  const int mp   = warp;       // M-part: batches [mp*16, mp*16+16), full K
  const int cta  = blockIdx.x;
  const int u0   = cta * 4;
  const float bl0 = __ldg(&bl[0]);

  float* misc = reinterpret_cast<float*>(smem + SM_MISC);
  // ---- init: weight fragments (hi|lo packed per uint4) + misc ----
  for (int idx = tid; idx < 3 * 512 * 16; idx += NTHR) {
    int m = idx >> 13, r = idx & 8191, k = r >> 4, gc = r & 15;
    int col = u0 + (gc & 3) + ((gc >> 2) << 9);
    const float* Wm = (m == 0) ? Wh2 : ((m == 1) ? Wx2 : Wh1);
    float v = Wm[k * 2048 + col];
    __half hi = __float2half_rn(v);
    __half lo = __float2half_rn(v - __half2float(hi));
    int q = k >> 4, kc = k & 15, nt = gc >> 3, n = gc & 7;
    int L = (n << 2) | ((kc & 7) >> 1), rg = kc >> 3, hf = kc & 1;
    __half* hp = reinterpret_cast<__half*>(smem + SM_B);
    int base = BOFF4(m, q, nt, L) * 4;  // uint index of the uint4
    hp[(base + 0 * 2 + rg) * 2 + hf] = hi;   // hi plane -> uints 0,1
    hp[(base + 1 * 2 + rg) * 2 + hf] = lo;   // lo plane -> uints 2,3
  }
  if (tid < 16) {
    int gc = tid;
    int col = u0 + (gc & 3) + ((gc >> 2) << 9);
    misc[gc]      = bx1[col] + bh1[col];
    misc[16 + gc] = bx2[col] + bh2[col];
    misc[32 + gc] = Wx1[col];
  }
  if (tid < 4) misc[48 + tid] = Wl[u0 + tid];
  __syncthreads();

  float c1s[4] = {0, 0, 0, 0}, c2s[4] = {0, 0, 0, 0};

  // h1(0) from x(0); zero slice of g_h2[1]
  if (tid < 256) {
    int b = tid;
    float x0 = __ldg(&seq[b * Tn]);
    float hv[4];
#pragma unroll
    for (int u = 0; u < 4; ++u) {
      float zi = fmaf(x0, misc[32 + u],      misc[u]);
      float zo = fmaf(x0, misc[32 + 8 + u],  misc[8 + u]);
      float zg = fmaf(x0, misc[32 + 12 + u], misc[12 + u]);
      float c = sigf(zi) * tanhf(zg);
      c1s[u] = c;
      hv[u] = sigf(zo) * tanhf(c);
    }
    h_write(g_h1[0], b, cta, hv);
  }
  for (int i = tid; i < 1024; i += NTHR) g_h2[1][cta * 1024 + i] = 0u;

  unsigned gen;
  asm volatile("ld.acquire.gpu.u32 %0, [%1];" : "=r"(gen) : "l"(&g_flags[cta]));
  grid_barrier(gen);

  const uint4* Bsm = reinterpret_cast<const uint4*>(smem + SM_B);

  for (int t = 0; t < TPn; ++t) {
    const bool pred = (t >= Tn - 1);

    const uint4* pH2 = reinterpret_cast<const uint4*>(g_h2[(t ^ 1) & 1]);
    const uint4* pH1 = reinterpret_cast<const uint4*>(g_h1[t & 1]);

    // main-phase o(t-1): owner reduces partials
    if (t >= 1 && t <= Tn - 1 && warp < 2) {
      int ob = 2 * cta + warp;
      float4 v = __ldcg(reinterpret_cast<const float4*>(g_opart + ob * NCTA) + lane);
      float p = v.x + v.y + v.z + v.w;
#pragma unroll
      for (int off = 16; off; off >>= 1) p += __shfl_xor_sync(0xffffffffu, p, off);
      if (lane == 0) g_out[(t - 1) * 256 + ob] = p;
    }

    float z2a[2][4], z1a[2][4];
#pragma unroll
    for (int i = 0; i < 8; ++i) {
      reinterpret_cast<float*>(z2a)[i] = 0.f;
      reinterpret_cast<float*>(z1a)[i] = 0.f;
    }

    // chunk cc = q*4 + ph ; ph: 0=h2hi, 1=h2lo, 2=h1hi, 3=h1lo
    auto loadA = [&](int cc) -> uint4 {
      int q = cc >> 2, ph = cc & 3;
      const uint4* base = (ph < 2) ? pH2 : pH1;
      return ldcg128(base + ((q * 2 + (ph & 1)) * 16 + mp) * 32 + lane);
    };

    uint4 Bq[6];
    auto loadBq = [&](int q) {
#pragma unroll
      for (int m = 0; m < 3; ++m)
#pragma unroll
        for (int nt = 0; nt < 2; ++nt)
          Bq[m * 2 + nt] = Bsm[BOFF4(m, q, nt, lane)];
    };

    auto compute = [&](int cc, const uint4& a) {
      int ph = cc & 3;
      if (ph == 0) {
#pragma unroll
        for (int nt = 0; nt < 2; ++nt) {
          mma16816(z2a[nt], a, Bq[nt].x, Bq[nt].y);
          mma16816(z2a[nt], a, Bq[nt].z, Bq[nt].w);
        }
      } else if (ph == 1) {
#pragma unroll
        for (int nt = 0; nt < 2; ++nt)
          mma16816(z2a[nt], a, Bq[nt].x, Bq[nt].y);
      } else if (ph == 2) {
#pragma unroll
        for (int nt = 0; nt < 2; ++nt) {
          mma16816(z2a[nt], a, Bq[2 + nt].x, Bq[2 + nt].y);
          mma16816(z2a[nt], a, Bq[2 + nt].z, Bq[2 + nt].w);
          mma16816(z1a[nt], a, Bq[4 + nt].x, Bq[4 + nt].y);
          mma16816(z1a[nt], a, Bq[4 + nt].z, Bq[4 + nt].w);
        }
      } else {
#pragma unroll
        for (int nt = 0; nt < 2; ++nt) {
          mma16816(z2a[nt], a, Bq[2 + nt].x, Bq[2 + nt].y);
          mma16816(z1a[nt], a, Bq[4 + nt].x, Bq[4 + nt].y);
        }
      }
    };

    // 128 tiny chunks, 12-deep register ring of A fragments, fully unrolled
    // (constant folding of ring index / phase / addresses)
    {
      uint4 ar[12];
#pragma unroll
      for (int i = 0; i < 12; ++i) ar[i] = loadA(i);
#pragma unroll
      for (int cc = 0; cc < 128; ++cc) {
        if ((cc & 3) == 0) loadBq(cc >> 2);
        compute(cc, ar[cc % 12]);
        if (cc < 116) ar[cc % 12] = loadA(cc + 12);
      }
    }

    // ---- each warp writes its z tiles straight to zbuf (no K-reduce) ----
    {
      float* zb = reinterpret_cast<float*>(smem + SM_Z);
#pragma unroll
      for (int nt = 0; nt < 2; ++nt)
#pragma unroll
        for (int ci = 0; ci < 4; ++ci) {
          int b  = mp * 16 + (lane >> 2) + 8 * (ci >> 1);
          int gc = nt * 8 + (lane & 3) * 2 + (ci & 1);
          zb[gc * 257 + b]        = z2a[nt][ci];
          zb[(16 + gc) * 257 + b] = z1a[nt][ci];
        }
    }
    __syncthreads();

    // ---- epilogue layer 2 -> h2(t), opart ----
    const float* zb = reinterpret_cast<const float*>(smem + SM_Z);
    if (tid < 256) {
      int b = tid;
      float hv[4], op = 0.f;
#pragma unroll
      for (int u = 0; u < 4; ++u) {
        float zi = zb[(u) * 257 + b]      + misc[16 + u];
        float zf = zb[(4 + u) * 257 + b]  + misc[16 + 4 + u];
        float zo = zb[(8 + u) * 257 + b]  + misc[16 + 8 + u];
        float zg = zb[(12 + u) * 257 + b] + misc[16 + 12 + u];
        float c = sigf(zf) * c2s[u] + sigf(zi) * tanhf(zg);
        c2s[u] = c;
        hv[u] = sigf(zo) * tanhf(c);
        op = fmaf(hv[u], misc[48 + u], op);
      }
      h_write(g_h2[t & 1], b, cta, hv);
      g_opart[b * NCTA + cta] = op;
    }

    // ---- next input ----
    float xnext = 0.f;
    if (!pred) {
      if (tid < 256) xnext = __ldg(&seq[tid * Tn + (t + 1)]);
    } else {
      grid_barrier(gen);
      if (warp < 2) {
        int ob = 2 * cta + warp;
        float4 v = __ldcg(reinterpret_cast<const float4*>(g_opart + ob * NCTA) + lane);
        float p = v.x + v.y + v.z + v.w;
#pragma unroll
        for (int off = 16; off; off >>= 1) p += __shfl_xor_sync(0xffffffffu, p, off);
        if (lane == 0) g_out[t * 256 + ob] = p;
      }
      grid_barrier(gen);
      if (tid < 256) xnext = __ldcg(&g_out[t * 256 + tid]) + bl0;
    }

    // ---- epilogue layer 1 -> h1(t+1) ----
    if (tid < 256) {
      int b = tid;
      float hv[4];
#pragma unroll
      for (int u = 0; u < 4; ++u) {
        float zi = fmaf(xnext, misc[32 + u],      zb[(16 + u) * 257 + b]      + misc[u]);
        float zf = fmaf(xnext, misc[32 + 4 + u],  zb[(16 + 4 + u) * 257 + b]  + misc[4 + u]);
        float zo = fmaf(xnext, misc[32 + 8 + u],  zb[(16 + 8 + u) * 257 + b]  + misc[8 + u]);
        float zg = fmaf(xnext, misc[32 + 12 + u], zb[(16 + 12 + u) * 257 + b] + misc[12 + u]);
        float c = sigf(zf) * c1s[u] + sigf(zi) * tanhf(zg);
        c1s[u] = c;
        hv[u] = sigf(zo) * tanhf(c);
      }
      h_write(g_h1[(t + 1) & 1], b, cta, hv);
    }
    grid_barrier(gen);
  }

  // out[b][tp] = o + bl
  for (int idx = cta * NTHR + tid; idx < TPn * 256; idx += NCTA * NTHR) {
    int b = idx / TPn, tp = idx - b * TPn;
    out[idx] = __ldcg(&g_out[tp * 256 + b]) + bl0;
  }
}

extern "C" void kernel_launch(void* const* d_in, const int* in_sizes, int n_in,
                              void* d_out, int out_size) {
  (void)in_sizes; (void)n_in; (void)out_size;
  const float* seq = (const float*)d_in[0];
  const float* Wx1 = (const float*)d_in[2];
  const float* bx1 = (const float*)d_in[3];
  const float* Wh1 = (const float*)d_in[4];
  const float* bh1 = (const float*)d_in[5];
  const float* Wx2 = (const float*)d_in[6];
  const float* bx2 = (const float*)d_in[7];
  const float* Wh2 = (const float*)d_in[8];
  const float* bh2 = (const float*)d_in[9];
  const float* Wl  = (const float*)d_in[10];
  const float* bl  = (const float*)d_in[11];

  cudaFuncSetAttribute(sine_rnn_kernel,
                       cudaFuncAttributeMaxDynamicSharedMemorySize, SM_TOTAL);
  sine_rnn_kernel<<<NCTA, NTHR, SM_TOTAL>>>(
      seq, Wx1, bx1, Wh1, bh1, Wx2, bx2, Wh2, bh2, Wl, bl, (float*)d_out);
}

// round 14
// speedup vs baseline: 2.1846x; 1.0589x over previous
#include <cuda_runtime.h>
#include <cuda_fp16.h>

#define NCTA 128
#define NTHR 512
#define Tn   512
#define TPn  544

// SMEM byte map
#define SM_B      0                 // 96KB weight fragments, uint4 = [hi0,hi1,lo0,lo1]
#define SM_Z      98304             // zbuf 32*257*4 = 32896 B
#define SM_MISC   (SM_Z + 32896)
#define SM_TOTAL  (SM_MISC + 256)

// uint4 index for B fragment block (m matrix, q k-chunk, nt n-tile, L lane)
#define BOFF4(m,q,nt,L) (((((m)*32+(q))*2+(nt))*32+(L)))

__device__ __align__(16) unsigned g_h1[2][131072];  // fp16 planes, A-frag order (hi used)
__device__ __align__(16) unsigned g_h2[2][131072];
__device__ float    g_opart[256 * NCTA];            // [b][cta]
__device__ float    g_out[TPn * 256];               // [t][b], raw (no bl)
__device__ unsigned g_flags[NCTA];

__device__ __forceinline__ float sigf(float x) { return 1.f / (1.f + __expf(-x)); }

__device__ __forceinline__ void mma16816(float* c, const uint4& a,
                                         unsigned b0, unsigned b1) {
  asm volatile(
      "mma.sync.aligned.m16n8k16.row.col.f32.f16.f16.f32 "
      "{%0,%1,%2,%3},{%4,%5,%6,%7},{%8,%9},{%0,%1,%2,%3};\n"
      : "+f"(c[0]), "+f"(c[1]), "+f"(c[2]), "+f"(c[3])
      : "r"(a.x), "r"(a.y), "r"(a.z), "r"(a.w), "r"(b0), "r"(b1));
}

__device__ __forceinline__ uint4 ldcg128(const uint4* p) {
  uint4 v;
  asm volatile("ld.global.cg.v4.u32 {%0,%1,%2,%3}, [%4];"
               : "=r"(v.x), "=r"(v.y), "=r"(v.z), "=r"(v.w) : "l"(p));
  return v;
}

__device__ __forceinline__ void grid_barrier(unsigned& gen) {
  __threadfence();
  __syncthreads();
  ++gen;
  if (threadIdx.x == 0)
    asm volatile("st.release.gpu.u32 [%0], %1;" :: "l"(&g_flags[blockIdx.x]), "r"(gen));
  if (threadIdx.x < NCTA) {
    unsigned v;
    do {
      asm volatile("ld.acquire.gpu.u32 %0, [%1];" : "=r"(v) : "l"(&g_flags[threadIdx.x]));
    } while ((int)(v - gen) < 0);
  }
  __syncthreads();
}

// write h[b][u0..u0+3] as fp16 hi plane in A-fragment order (lo plane unused)
__device__ __forceinline__ void h_write(unsigned* gb, int b, int cta, const float* hv) {
  int q = cta >> 2, kcb = (cta & 3) * 4, mtg = b >> 4;
  __half hh[4];
#pragma unroll
  for (int u = 0; u < 4; ++u) hh[u] = __float2half_rn(hv[u]);
#pragma unroll
  for (int j = 0; j < 2; ++j) {
    int kc0 = kcb + 2 * j;
    int L   = ((b & 7) << 2) | ((kc0 & 7) >> 1);
    int rg  = ((b >> 3) & 1) | ((kc0 >> 3) << 1);
    __half2 vh = __halves2half2(hh[2 * j], hh[2 * j + 1]);
    gb[((q * 2 + 0) * 16 + mtg) * 128 + L * 4 + rg] = *reinterpret_cast<unsigned*>(&vh);
  }
}

__global__ void __launch_bounds__(NTHR, 1) sine_rnn_kernel(
    const float* __restrict__ seq,
    const float* __restrict__ Wx1, const float* __restrict__ bx1,
    const float* __restrict__ Wh1, const float* __restrict__ bh1,
    const float* __restrict__ Wx2, const float* __restrict__ bx2,
    const float* __restrict__ Wh2, const float* __restrict__ bh2,
    const float* __restrict__ Wl,  const float* __restrict__ bl,
    float* __restrict__ out)
{
  extern __shared__ char smem[];
  const int tid  = threadIdx.x;
  const int lane = tid & 31;
  const int warp = tid >> 5;
  const int mp   = warp;       // M-part: batches [mp*16, mp*16+16), full K
  const int cta  = blockIdx.x;
  const int u0   = cta * 4;
  const float bl0 = __ldg(&bl[0]);

  float* misc = reinterpret_cast<float*>(smem + SM_MISC);
  // ---- init: weight fragments (hi|lo packed per uint4) + misc ----
  for (int idx = tid; idx < 3 * 512 * 16; idx += NTHR) {
    int m = idx >> 13, r = idx & 8191, k = r >> 4, gc = r & 15;
    int col = u0 + (gc & 3) + ((gc >> 2) << 9);
    const float* Wm = (m == 0) ? Wh2 : ((m == 1) ? Wx2 : Wh1);
    float v = Wm[k * 2048 + col];
    __half hi = __float2half_rn(v);
    __half lo = __float2half_rn(v - __half2float(hi));
    int q = k >> 4, kc = k & 15, nt = gc >> 3, n = gc & 7;
    int L = (n << 2) | ((kc & 7) >> 1), rg = kc >> 3, hf = kc & 1;
    __half* hp = reinterpret_cast<__half*>(smem + SM_B);
    int base = BOFF4(m, q, nt, L) * 4;  // uint index of the uint4
    hp[(base + 0 * 2 + rg) * 2 + hf] = hi;   // hi plane -> uints 0,1
    hp[(base + 1 * 2 + rg) * 2 + hf] = lo;   // lo plane -> uints 2,3
  }
  if (tid < 16) {
    int gc = tid;
    int col = u0 + (gc & 3) + ((gc >> 2) << 9);
    misc[gc]      = bx1[col] + bh1[col];
    misc[16 + gc] = bx2[col] + bh2[col];
    misc[32 + gc] = Wx1[col];
  }
  if (tid < 4) misc[48 + tid] = Wl[u0 + tid];
  __syncthreads();

  float c1s[4] = {0, 0, 0, 0}, c2s[4] = {0, 0, 0, 0};

  // h1(0) from x(0); zero slice of g_h2[1]
  if (tid < 256) {
    int b = tid;
    float x0 = __ldg(&seq[b * Tn]);
    float hv[4];
#pragma unroll
    for (int u = 0; u < 4; ++u) {
      float zi = fmaf(x0, misc[32 + u],      misc[u]);
      float zo = fmaf(x0, misc[32 + 8 + u],  misc[8 + u]);
      float zg = fmaf(x0, misc[32 + 12 + u], misc[12 + u]);
      float c = sigf(zi) * tanhf(zg);
      c1s[u] = c;
      hv[u] = sigf(zo) * tanhf(c);
    }
    h_write(g_h1[0], b, cta, hv);
  }
  for (int i = tid; i < 1024; i += NTHR) g_h2[1][cta * 1024 + i] = 0u;

  unsigned gen;
  asm volatile("ld.acquire.gpu.u32 %0, [%1];" : "=r"(gen) : "l"(&g_flags[cta]));
  grid_barrier(gen);

  const uint4* Bsm = reinterpret_cast<const uint4*>(smem + SM_B);

  for (int t = 0; t < TPn; ++t) {
    const bool pred = (t >= Tn - 1);

    const uint4* pH2 = reinterpret_cast<const uint4*>(g_h2[(t ^ 1) & 1]);
    const uint4* pH1 = reinterpret_cast<const uint4*>(g_h1[t & 1]);

    // main-phase o(t-1): owner reduces partials
    if (t >= 1 && t <= Tn - 1 && warp < 2) {
      int ob = 2 * cta + warp;
      float4 v = __ldcg(reinterpret_cast<const float4*>(g_opart + ob * NCTA) + lane);
      float p = v.x + v.y + v.z + v.w;
#pragma unroll
      for (int off = 16; off; off >>= 1) p += __shfl_xor_sync(0xffffffffu, p, off);
      if (lane == 0) g_out[(t - 1) * 256 + ob] = p;
    }

    float z2a[2][4], z1a[2][4];
#pragma unroll
    for (int i = 0; i < 8; ++i) {
      reinterpret_cast<float*>(z2a)[i] = 0.f;
      reinterpret_cast<float*>(z1a)[i] = 0.f;
    }

    // chunk cc = q*2 + ph ; ph: 0 = h2 hi (Wh2), 1 = h1 hi (Wx2 + Wh1)
    auto loadA = [&](int cc) -> uint4 {
      int q = cc >> 1, ph = cc & 1;
      const uint4* base = ph ? pH1 : pH2;
      return ldcg128(base + ((q * 2) * 16 + mp) * 32 + lane);
    };

    uint4 Bq[6];
    auto loadBq = [&](int q) {
#pragma unroll
      for (int m = 0; m < 3; ++m)
#pragma unroll
        for (int nt = 0; nt < 2; ++nt)
          Bq[m * 2 + nt] = Bsm[BOFF4(m, q, nt, lane)];
    };

    auto compute = [&](int cc, const uint4& a) {
      if ((cc & 1) == 0) {
        // h2hi x (Wh2 hi + Wh2 lo) -> z2
#pragma unroll
        for (int nt = 0; nt < 2; ++nt) {
          mma16816(z2a[nt], a, Bq[nt].x, Bq[nt].y);
          mma16816(z2a[nt], a, Bq[nt].z, Bq[nt].w);
        }
      } else {
        // h1hi x (Wx2 hi+lo) -> z2 ; h1hi x (Wh1 hi+lo) -> z1
#pragma unroll
        for (int nt = 0; nt < 2; ++nt) {
          mma16816(z2a[nt], a, Bq[2 + nt].x, Bq[2 + nt].y);
          mma16816(z2a[nt], a, Bq[2 + nt].z, Bq[2 + nt].w);
          mma16816(z1a[nt], a, Bq[4 + nt].x, Bq[4 + nt].y);
          mma16816(z1a[nt], a, Bq[4 + nt].z, Bq[4 + nt].w);
        }
      }
    };

    // 64 chunks, 12-deep register ring of A fragments, fully unrolled
    {
      uint4 ar[12];
#pragma unroll
      for (int i = 0; i < 12; ++i) ar[i] = loadA(i);
#pragma unroll
      for (int cc = 0; cc < 64; ++cc) {
        if ((cc & 1) == 0) loadBq(cc >> 1);
        compute(cc, ar[cc % 12]);
        if (cc < 52) ar[cc % 12] = loadA(cc + 12);
      }
    }

    // ---- each warp writes its z tiles straight to zbuf (no K-reduce) ----
    {
      float* zb = reinterpret_cast<float*>(smem + SM_Z);
#pragma unroll
      for (int nt = 0; nt < 2; ++nt)
#pragma unroll
        for (int ci = 0; ci < 4; ++ci) {
          int b  = mp * 16 + (lane >> 2) + 8 * (ci >> 1);
          int gc = nt * 8 + (lane & 3) * 2 + (ci & 1);
          zb[gc * 257 + b]        = z2a[nt][ci];
          zb[(16 + gc) * 257 + b] = z1a[nt][ci];
        }
    }
    __syncthreads();

    // ---- epilogue layer 2 -> h2(t), opart ----
    const float* zb = reinterpret_cast<const float*>(smem + SM_Z);
    if (tid < 256) {
      int b = tid;
      float hv[4], op = 0.f;
#pragma unroll
      for (int u = 0; u < 4; ++u) {
        float zi = zb[(u) * 257 + b]      + misc[16 + u];
        float zf = zb[(4 + u) * 257 + b]  + misc[16 + 4 + u];
        float zo = zb[(8 + u) * 257 + b]  + misc[16 + 8 + u];
        float zg = zb[(12 + u) * 257 + b] + misc[16 + 12 + u];
        float c = sigf(zf) * c2s[u] + sigf(zi) * tanhf(zg);
        c2s[u] = c;
        hv[u] = sigf(zo) * tanhf(c);
        op = fmaf(hv[u], misc[48 + u], op);
      }
      h_write(g_h2[t & 1], b, cta, hv);
      g_opart[b * NCTA + cta] = op;
    }

    // ---- next input ----
    float xnext = 0.f;
    if (!pred) {
      if (tid < 256) xnext = __ldg(&seq[tid * Tn + (t + 1)]);
    } else {
      grid_barrier(gen);
      if (warp < 2) {
        int ob = 2 * cta + warp;
        float4 v = __ldcg(reinterpret_cast<const float4*>(g_opart + ob * NCTA) + lane);
        float p = v.x + v.y + v.z + v.w;
#pragma unroll
        for (int off = 16; off; off >>= 1) p += __shfl_xor_sync(0xffffffffu, p, off);
        if (lane == 0) g_out[t * 256 + ob] = p;
      }
      grid_barrier(gen);
      if (tid < 256) xnext = __ldcg(&g_out[t * 256 + tid]) + bl0;
    }

    // ---- epilogue layer 1 -> h1(t+1) ----
    if (tid < 256) {
      int b = tid;
      float hv[4];
#pragma unroll
      for (int u = 0; u < 4; ++u) {
        float zi = fmaf(xnext, misc[32 + u],      zb[(16 + u) * 257 + b]      + misc[u]);
        float zf = fmaf(xnext, misc[32 + 4 + u],  zb[(16 + 4 + u) * 257 + b]  + misc[4 + u]);
        float zo = fmaf(xnext, misc[32 + 8 + u],  zb[(16 + 8 + u) * 257 + b]  + misc[8 + u]);
        float zg = fmaf(xnext, misc[32 + 12 + u], zb[(16 + 12 + u) * 257 + b] + misc[12 + u]);
        float c = sigf(zf) * c1s[u] + sigf(zi) * tanhf(zg);
        c1s[u] = c;
        hv[u] = sigf(zo) * tanhf(c);
      }
      h_write(g_h1[(t + 1) & 1], b, cta, hv);
    }
    grid_barrier(gen);
  }

  // out[b][tp] = o + bl
  for (int idx = cta * NTHR + tid; idx < TPn * 256; idx += NCTA * NTHR) {
    int b = idx / TPn, tp = idx - b * TPn;
    out[idx] = __ldcg(&g_out[tp * 256 + b]) + bl0;
  }
}

extern "C" void kernel_launch(void* const* d_in, const int* in_sizes, int n_in,
                              void* d_out, int out_size) {
  (void)in_sizes; (void)n_in; (void)out_size;
  const float* seq = (const float*)d_in[0];
  const float* Wx1 = (const float*)d_in[2];
  const float* bx1 = (const float*)d_in[3];
  const float* Wh1 = (const float*)d_in[4];
  const float* bh1 = (const float*)d_in[5];
  const float* Wx2 = (const float*)d_in[6];
  const float* bx2 = (const float*)d_in[7];
  const float* Wh2 = (const float*)d_in[8];
  const float* bh2 = (const float*)d_in[9];
  const float* Wl  = (const float*)d_in[10];
  const float* bl  = (const float*)d_in[11];

  cudaFuncSetAttribute(sine_rnn_kernel,
                       cudaFuncAttributeMaxDynamicSharedMemorySize, SM_TOTAL);
  sine_rnn_kernel<<<NCTA, NTHR, SM_TOTAL>>>(
      seq, Wx1, bx1, Wh1, bh1, Wx2, bx2, Wh2, bh2, Wl, bl, (float*)d_out);
}

// round 15
// speedup vs baseline: 2.6530x; 1.2144x over previous
#include <cuda_runtime.h>
#include <cuda_fp16.h>

#define NCTA 128
#define NTHR 512
#define Tn   512
#define TPn  544

// SMEM byte map
#define SM_B      0                 // 96KB weight fragments, uint4 = [hi0,hi1,lo0,lo1]
#define SM_SLOT   98304             // 32KB K-reduce slot (kp1 -> kp0)
#define SM_Z      131072            // zbuf 32*257*4 = 32896 B
#define SM_MISC   (SM_Z + 32896)
#define SM_TOTAL  (SM_MISC + 256)

// uint4 index for B fragment block (m matrix, q k-chunk, nt n-tile, L lane)
#define BOFF4(m,q,nt,L) (((((m)*32+(q))*2+(nt))*32+(L)))

__device__ __align__(16) unsigned g_h1[2][131072];  // fp16 hi plane, A-frag order
__device__ __align__(16) unsigned g_h2[2][131072];
__device__ float    g_opart[256 * NCTA];            // [b][cta]
__device__ float    g_out[TPn * 256];               // [t][b], raw (no bl)
__device__ unsigned g_flags[NCTA];

__device__ __forceinline__ float sigf(float x) { return 1.f / (1.f + __expf(-x)); }

__device__ __forceinline__ void mma16816(float* c, const uint4& a,
                                         unsigned b0, unsigned b1) {
  asm volatile(
      "mma.sync.aligned.m16n8k16.row.col.f32.f16.f16.f32 "
      "{%0,%1,%2,%3},{%4,%5,%6,%7},{%8,%9},{%0,%1,%2,%3};\n"
      : "+f"(c[0]), "+f"(c[1]), "+f"(c[2]), "+f"(c[3])
      : "r"(a.x), "r"(a.y), "r"(a.z), "r"(a.w), "r"(b0), "r"(b1));
}

__device__ __forceinline__ uint4 ldcg128(const uint4* p) {
  uint4 v;
  asm volatile("ld.global.cg.v4.u32 {%0,%1,%2,%3}, [%4];"
               : "=r"(v.x), "=r"(v.y), "=r"(v.z), "=r"(v.w) : "l"(p));
  return v;
}

__device__ __forceinline__ void grid_barrier(unsigned& gen) {
  __threadfence();
  __syncthreads();
  ++gen;
  if (threadIdx.x == 0)
    asm volatile("st.release.gpu.u32 [%0], %1;" :: "l"(&g_flags[blockIdx.x]), "r"(gen));
  if (threadIdx.x < NCTA) {
    unsigned v;
    do {
      asm volatile("ld.acquire.gpu.u32 %0, [%1];" : "=r"(v) : "l"(&g_flags[threadIdx.x]));
    } while ((int)(v - gen) < 0);
  }
  __syncthreads();
}

// write h[b][u0..u0+3] as fp16 hi plane in A-fragment order
__device__ __forceinline__ void h_write(unsigned* gb, int b, int cta, const float* hv) {
  int q = cta >> 2, kcb = (cta & 3) * 4, mtg = b >> 4;
  __half hh[4];
#pragma unroll
  for (int u = 0; u < 4; ++u) hh[u] = __float2half_rn(hv[u]);
#pragma unroll
  for (int j = 0; j < 2; ++j) {
    int kc0 = kcb + 2 * j;
    int L   = ((b & 7) << 2) | ((kc0 & 7) >> 1);
    int rg  = ((b >> 3) & 1) | ((kc0 >> 3) << 1);
    __half2 vh = __halves2half2(hh[2 * j], hh[2 * j + 1]);
    gb[((q * 2 + 0) * 16 + mtg) * 128 + L * 4 + rg] = *reinterpret_cast<unsigned*>(&vh);
  }
}

__global__ void __launch_bounds__(NTHR, 1) sine_rnn_kernel(
    const float* __restrict__ seq,
    const float* __restrict__ Wx1, const float* __restrict__ bx1,
    const float* __restrict__ Wh1, const float* __restrict__ bh1,
    const float* __restrict__ Wx2, const float* __restrict__ bx2,
    const float* __restrict__ Wh2, const float* __restrict__ bh2,
    const float* __restrict__ Wl,  const float* __restrict__ bl,
    float* __restrict__ out)
{
  extern __shared__ char smem[];
  const int tid  = threadIdx.x;
  const int lane = tid & 31;
  const int warp = tid >> 5;
  const int kp   = warp >> 3;   // K-part (q in [kp*16, kp*16+16))
  const int mpp  = warp & 7;    // M-part: batches [mpp*32, mpp*32+32)
  const int cta  = blockIdx.x;
  const int u0   = cta * 4;
  const float bl0 = __ldg(&bl[0]);

  float* misc = reinterpret_cast<float*>(smem + SM_MISC);
  // ---- init: weight fragments (hi|lo packed per uint4) + misc ----
  for (int idx = tid; idx < 3 * 512 * 16; idx += NTHR) {
    int m = idx >> 13, r = idx & 8191, k = r >> 4, gc = r & 15;
    int col = u0 + (gc & 3) + ((gc >> 2) << 9);
    const float* Wm = (m == 0) ? Wh2 : ((m == 1) ? Wx2 : Wh1);
    float v = Wm[k * 2048 + col];
    __half hi = __float2half_rn(v);
    __half lo = __float2half_rn(v - __half2float(hi));
    int q = k >> 4, kc = k & 15, nt = gc >> 3, n = gc & 7;
    int L = (n << 2) | ((kc & 7) >> 1), rg = kc >> 3, hf = kc & 1;
    __half* hp = reinterpret_cast<__half*>(smem + SM_B);
    int base = BOFF4(m, q, nt, L) * 4;
    hp[(base + 0 * 2 + rg) * 2 + hf] = hi;
    hp[(base + 1 * 2 + rg) * 2 + hf] = lo;
  }
  if (tid < 16) {
    int gc = tid;
    int col = u0 + (gc & 3) + ((gc >> 2) << 9);
    misc[gc]      = bx1[col] + bh1[col];
    misc[16 + gc] = bx2[col] + bh2[col];
    misc[32 + gc] = Wx1[col];
  }
  if (tid < 4) misc[48 + tid] = Wl[u0 + tid];
  __syncthreads();

  float c1s[4] = {0, 0, 0, 0}, c2s[4] = {0, 0, 0, 0};

  // h1(0) from x(0); zero slice of g_h2[1]
  if (tid < 256) {
    int b = tid;
    float x0 = __ldg(&seq[b * Tn]);
    float hv[4];
#pragma unroll
    for (int u = 0; u < 4; ++u) {
      float zi = fmaf(x0, misc[32 + u],      misc[u]);
      float zo = fmaf(x0, misc[32 + 8 + u],  misc[8 + u]);
      float zg = fmaf(x0, misc[32 + 12 + u], misc[12 + u]);
      float c = sigf(zi) * tanhf(zg);
      c1s[u] = c;
      hv[u] = sigf(zo) * tanhf(c);
    }
    h_write(g_h1[0], b, cta, hv);
  }
  for (int i = tid; i < 1024; i += NTHR) g_h2[1][cta * 1024 + i] = 0u;

  unsigned gen;
  asm volatile("ld.acquire.gpu.u32 %0, [%1];" : "=r"(gen) : "l"(&g_flags[cta]));
  grid_barrier(gen);

  const uint4* Bsm = reinterpret_cast<const uint4*>(smem + SM_B);

  for (int t = 0; t < TPn; ++t) {
    const bool pred = (t >= Tn - 1);

    const uint4* pH2 = reinterpret_cast<const uint4*>(g_h2[(t ^ 1) & 1]);
    const uint4* pH1 = reinterpret_cast<const uint4*>(g_h1[t & 1]);

    float z2a[2][2][4], z1a[2][2][4];   // [mt][nt][ci]
#pragma unroll
    for (int i = 0; i < 16; ++i) {
      reinterpret_cast<float*>(z2a)[i] = 0.f;
      reinterpret_cast<float*>(z1a)[i] = 0.f;
    }

    // chunk cc = (local q)*2 + ph ; ph: 0 = h2 hi (Wh2), 1 = h1 hi (Wx2+Wh1)
    auto loadA = [&](int cc, uint4* a) {
      int q = kp * 16 + (cc >> 1), ph = cc & 1;
      const uint4* g = (ph ? pH1 : pH2) + ((q * 2) * 16 + mpp * 2) * 32 + lane;
      a[0] = ldcg128(g);
      a[1] = ldcg128(g + 32);
    };

    uint4 Bq[6];
    auto loadBq = [&](int q) {
#pragma unroll
      for (int m = 0; m < 3; ++m)
#pragma unroll
        for (int nt = 0; nt < 2; ++nt)
          Bq[m * 2 + nt] = Bsm[BOFF4(m, q, nt, lane)];
    };

    auto compute = [&](int cc, const uint4* a) {
      if ((cc & 1) == 0) {
#pragma unroll
        for (int mt = 0; mt < 2; ++mt)
#pragma unroll
          for (int nt = 0; nt < 2; ++nt) {
            mma16816(z2a[mt][nt], a[mt], Bq[nt].x, Bq[nt].y);
            mma16816(z2a[mt][nt], a[mt], Bq[nt].z, Bq[nt].w);
          }
      } else {
#pragma unroll
        for (int mt = 0; mt < 2; ++mt)
#pragma unroll
          for (int nt = 0; nt < 2; ++nt) {
            mma16816(z2a[mt][nt], a[mt], Bq[2 + nt].x, Bq[2 + nt].y);
            mma16816(z2a[mt][nt], a[mt], Bq[2 + nt].z, Bq[2 + nt].w);
            mma16816(z1a[mt][nt], a[mt], Bq[4 + nt].x, Bq[4 + nt].y);
            mma16816(z1a[mt][nt], a[mt], Bq[4 + nt].z, Bq[4 + nt].w);
          }
      }
    };

    // prime 6-deep ring, then overlap o(t-1) reduce with in-flight LDGs
    uint4 ar[6][2];
#pragma unroll
    for (int i = 0; i < 6; ++i) loadA(i, ar[i]);

    if (t >= 1 && t <= Tn - 1 && warp < 2) {
      int ob = 2 * cta + warp;
      float4 v = __ldcg(reinterpret_cast<const float4*>(g_opart + ob * NCTA) + lane);
      float p = v.x + v.y + v.z + v.w;
#pragma unroll
      for (int off = 16; off; off >>= 1) p += __shfl_xor_sync(0xffffffffu, p, off);
      if (lane == 0) g_out[(t - 1) * 256 + ob] = p;
    }

    // 32 chunks (own K half), fully unrolled
#pragma unroll
    for (int cc = 0; cc < 32; ++cc) {
      if ((cc & 1) == 0) loadBq(kp * 16 + (cc >> 1));
      compute(cc, ar[cc % 6]);
      if (cc < 26) loadA(cc + 6, ar[cc % 6]);
    }

    // ---- K-reduce: kp1 -> slot, kp0 adds, kp0 writes zbuf ----
    {
      int tk = mpp * 32 + lane;
      float2* slot = reinterpret_cast<float2*>(smem + SM_SLOT);
      if (kp == 1) {
        const float* zf2 = reinterpret_cast<const float*>(z2a);
        const float* zf1 = reinterpret_cast<const float*>(z1a);
#pragma unroll
        for (int i = 0; i < 8; ++i)
          slot[i * 256 + tk] = make_float2(zf2[2 * i], zf2[2 * i + 1]);
#pragma unroll
        for (int i = 0; i < 8; ++i)
          slot[(8 + i) * 256 + tk] = make_float2(zf1[2 * i], zf1[2 * i + 1]);
      }
      __syncthreads();
      if (kp == 0) {
        float* zf2 = reinterpret_cast<float*>(z2a);
        float* zf1 = reinterpret_cast<float*>(z1a);
#pragma unroll
        for (int i = 0; i < 8; ++i) {
          float2 v = slot[i * 256 + tk];
          zf2[2 * i] += v.x; zf2[2 * i + 1] += v.y;
        }
#pragma unroll
        for (int i = 0; i < 8; ++i) {
          float2 v = slot[(8 + i) * 256 + tk];
          zf1[2 * i] += v.x; zf1[2 * i + 1] += v.y;
        }
        float* zb = reinterpret_cast<float*>(smem + SM_Z);
#pragma unroll
        for (int mt = 0; mt < 2; ++mt)
#pragma unroll
          for (int nt = 0; nt < 2; ++nt)
#pragma unroll
            for (int ci = 0; ci < 4; ++ci) {
              int b  = mpp * 32 + mt * 16 + (lane >> 2) + 8 * (ci >> 1);
              int gc = nt * 8 + (lane & 3) * 2 + (ci & 1);
              zb[gc * 257 + b]        = z2a[mt][nt][ci];
              zb[(16 + gc) * 257 + b] = z1a[mt][nt][ci];
            }
      }
    }
    __syncthreads();

    // ---- epilogue layer 2 -> h2(t), opart ----
    const float* zb = reinterpret_cast<const float*>(smem + SM_Z);
    if (tid < 256) {
      int b = tid;
      float hv[4], op = 0.f;
#pragma unroll
      for (int u = 0; u < 4; ++u) {
        float zi = zb[(u) * 257 + b]      + misc[16 + u];
        float zf = zb[(4 + u) * 257 + b]  + misc[16 + 4 + u];
        float zo = zb[(8 + u) * 257 + b]  + misc[16 + 8 + u];
        float zg = zb[(12 + u) * 257 + b] + misc[16 + 12 + u];
        float c = sigf(zf) * c2s[u] + sigf(zi) * tanhf(zg);
        c2s[u] = c;
        hv[u] = sigf(zo) * tanhf(c);
        op = fmaf(hv[u], misc[48 + u], op);
      }
      h_write(g_h2[t & 1], b, cta, hv);
      g_opart[b * NCTA + cta] = op;
    }

    // ---- next input ----
    float xnext = 0.f;
    if (!pred) {
      if (tid < 256) xnext = __ldg(&seq[tid * Tn + (t + 1)]);
    } else {
      grid_barrier(gen);
      if (warp < 2) {
        int ob = 2 * cta + warp;
        float4 v = __ldcg(reinterpret_cast<const float4*>(g_opart + ob * NCTA) + lane);
        float p = v.x + v.y + v.z + v.w;
#pragma unroll
        for (int off = 16; off; off >>= 1) p += __shfl_xor_sync(0xffffffffu, p, off);
        if (lane == 0) g_out[t * 256 + ob] = p;
      }
      grid_barrier(gen);
      if (tid < 256) xnext = __ldcg(&g_out[t * 256 + tid]) + bl0;
    }

    // ---- epilogue layer 1 -> h1(t+1) ----
    if (tid < 256) {
      int b = tid;
      float hv[4];
#pragma unroll
      for (int u = 0; u < 4; ++u) {
        float zi = fmaf(xnext, misc[32 + u],      zb[(16 + u) * 257 + b]      + misc[u]);
        float zf = fmaf(xnext, misc[32 + 4 + u],  zb[(16 + 4 + u) * 257 + b]  + misc[4 + u]);
        float zo = fmaf(xnext, misc[32 + 8 + u],  zb[(16 + 8 + u) * 257 + b]  + misc[8 + u]);
        float zg = fmaf(xnext, misc[32 + 12 + u], zb[(16 + 12 + u) * 257 + b] + misc[12 + u]);
        float c = sigf(zf) * c1s[u] + sigf(zi) * tanhf(zg);
        c1s[u] = c;
        hv[u] = sigf(zo) * tanhf(c);
      }
      h_write(g_h1[(t + 1) & 1], b, cta, hv);
    }
    grid_barrier(gen);
  }

  // out[b][tp] = o + bl
  for (int idx = cta * NTHR + tid; idx < TPn * 256; idx += NCTA * NTHR) {
    int b = idx / TPn, tp = idx - b * TPn;
    out[idx] = __ldcg(&g_out[tp * 256 + b]) + bl0;
  }
}

extern "C" void kernel_launch(void* const* d_in, const int* in_sizes, int n_in,
                              void* d_out, int out_size) {
  (void)in_sizes; (void)n_in; (void)out_size;
  const float* seq = (const float*)d_in[0];
  const float* Wx1 = (const float*)d_in[2];
  const float* bx1 = (const float*)d_in[3];
  const float* Wh1 = (const float*)d_in[4];
  const float* bh1 = (const float*)d_in[5];
  const float* Wx2 = (const float*)d_in[6];
  const float* bx2 = (const float*)d_in[7];
  const float* Wh2 = (const float*)d_in[8];
  const float* bh2 = (const float*)d_in[9];
  const float* Wl  = (const float*)d_in[10];
  const float* bl  = (const float*)d_in[11];

  cudaFuncSetAttribute(sine_rnn_kernel,
                       cudaFuncAttributeMaxDynamicSharedMemorySize, SM_TOTAL);
  sine_rnn_kernel<<<NCTA, NTHR, SM_TOTAL>>>(
      seq, Wx1, bx1, Wh1, bh1, Wx2, bx2, Wh2, bh2, Wl, bl, (float*)d_out);
}

// round 16
// speedup vs baseline: 3.0406x; 1.1461x over previous
#include <cuda_runtime.h>
#include <cuda_fp16.h>

#define NCTA 128
#define NTHR 512
#define Tn   512
#define TPn  544

// SMEM byte map
#define SM_B      0                 // 48KB weight fragments (fp16 hi only), uint2
#define SM_SLOT   49152             // 32KB K-reduce slot (kp1 -> kp0)
#define SM_Z      81920             // zbuf 32*257*4 = 32896 B
#define SM_MISC   (SM_Z + 32896)
#define SM_TOTAL  (SM_MISC + 256)

// uint2 index for B fragment block (m matrix, q k-chunk, nt n-tile, L lane)
#define BOFF2(m,q,nt,L) (((((m)*32+(q))*2+(nt))*32+(L)))

__device__ __align__(16) unsigned g_h1[2][131072];  // fp16 hi plane, A-frag order
__device__ __align__(16) unsigned g_h2[2][131072];
__device__ float    g_opart[256 * NCTA];            // [b][cta]
__device__ float    g_out[TPn * 256];               // [t][b], raw (no bl)
__device__ unsigned g_flags[NCTA];

__device__ __forceinline__ float sigf(float x) { return 1.f / (1.f + __expf(-x)); }
__device__ __forceinline__ float tanhf_fast(float x) {
  float e = __expf(2.f * x);                  // +inf / 0 at tails -> +-1 exactly
  return 1.f - __fdividef(2.f, e + 1.f);
}

__device__ __forceinline__ void mma16816(float* c, const uint4& a,
                                         unsigned b0, unsigned b1) {
  asm volatile(
      "mma.sync.aligned.m16n8k16.row.col.f32.f16.f16.f32 "
      "{%0,%1,%2,%3},{%4,%5,%6,%7},{%8,%9},{%0,%1,%2,%3};\n"
      : "+f"(c[0]), "+f"(c[1]), "+f"(c[2]), "+f"(c[3])
      : "r"(a.x), "r"(a.y), "r"(a.z), "r"(a.w), "r"(b0), "r"(b1));
}

__device__ __forceinline__ uint4 ldcg128(const uint4* p) {
  uint4 v;
  asm volatile("ld.global.cg.v4.u32 {%0,%1,%2,%3}, [%4];"
               : "=r"(v.x), "=r"(v.y), "=r"(v.z), "=r"(v.w) : "l"(p));
  return v;
}

__device__ __forceinline__ void grid_barrier(unsigned& gen) {
  __threadfence();
  __syncthreads();
  ++gen;
  if (threadIdx.x == 0)
    asm volatile("st.release.gpu.u32 [%0], %1;" :: "l"(&g_flags[blockIdx.x]), "r"(gen));
  if (threadIdx.x < NCTA) {
    unsigned v;
    do {
      asm volatile("ld.acquire.gpu.u32 %0, [%1];" : "=r"(v) : "l"(&g_flags[threadIdx.x]));
    } while ((int)(v - gen) < 0);
  }
  __syncthreads();
}

// write h[b][u0..u0+3] as fp16 hi plane in A-fragment order
__device__ __forceinline__ void h_write(unsigned* gb, int b, int cta, const float* hv) {
  int q = cta >> 2, kcb = (cta & 3) * 4, mtg = b >> 4;
  __half hh[4];
#pragma unroll
  for (int u = 0; u < 4; ++u) hh[u] = __float2half_rn(hv[u]);
#pragma unroll
  for (int j = 0; j < 2; ++j) {
    int kc0 = kcb + 2 * j;
    int L   = ((b & 7) << 2) | ((kc0 & 7) >> 1);
    int rg  = ((b >> 3) & 1) | ((kc0 >> 3) << 1);
    __half2 vh = __halves2half2(hh[2 * j], hh[2 * j + 1]);
    gb[((q * 2 + 0) * 16 + mtg) * 128 + L * 4 + rg] = *reinterpret_cast<unsigned*>(&vh);
  }
}

__global__ void __launch_bounds__(NTHR, 1) sine_rnn_kernel(
    const float* __restrict__ seq,
    const float* __restrict__ Wx1, const float* __restrict__ bx1,
    const float* __restrict__ Wh1, const float* __restrict__ bh1,
    const float* __restrict__ Wx2, const float* __restrict__ bx2,
    const float* __restrict__ Wh2, const float* __restrict__ bh2,
    const float* __restrict__ Wl,  const float* __restrict__ bl,
    float* __restrict__ out)
{
  extern __shared__ char smem[];
  const int tid  = threadIdx.x;
  const int lane = tid & 31;
  const int warp = tid >> 5;
  const int kp   = warp >> 3;   // K-part (q in [kp*16, kp*16+16))
  const int mpp  = warp & 7;    // M-part: batches [mpp*32, mpp*32+32)
  const int cta  = blockIdx.x;
  const int u0   = cta * 4;
  const float bl0 = __ldg(&bl[0]);

  float* misc = reinterpret_cast<float*>(smem + SM_MISC);
  // ---- init: weight fragments (fp16 hi only) + misc ----
  for (int idx = tid; idx < 3 * 512 * 16; idx += NTHR) {
    int m = idx >> 13, r = idx & 8191, k = r >> 4, gc = r & 15;
    int col = u0 + (gc & 3) + ((gc >> 2) << 9);
    const float* Wm = (m == 0) ? Wh2 : ((m == 1) ? Wx2 : Wh1);
    float v = Wm[k * 2048 + col];
    __half hi = __float2half_rn(v);
    int q = k >> 4, kc = k & 15, nt = gc >> 3, n = gc & 7;
    int L = (n << 2) | ((kc & 7) >> 1), rg = kc >> 3, hf = kc & 1;
    __half* hp = reinterpret_cast<__half*>(smem + SM_B);
    int base = BOFF2(m, q, nt, L) * 2;   // uint index of the uint2
    hp[(base + rg) * 2 + hf] = hi;
  }
  if (tid < 16) {
    int gc = tid;
    int col = u0 + (gc & 3) + ((gc >> 2) << 9);
    misc[gc]      = bx1[col] + bh1[col];
    misc[16 + gc] = bx2[col] + bh2[col];
    misc[32 + gc] = Wx1[col];
  }
  if (tid < 4) misc[48 + tid] = Wl[u0 + tid];
  __syncthreads();

  float c1s[4] = {0, 0, 0, 0}, c2s[4] = {0, 0, 0, 0};

  // h1(0) from x(0); zero slice of g_h2[1]
  if (tid < 256) {
    int b = tid;
    float x0 = __ldg(&seq[b * Tn]);
    float hv[4];
#pragma unroll
    for (int u = 0; u < 4; ++u) {
      float zi = fmaf(x0, misc[32 + u],      misc[u]);
      float zo = fmaf(x0, misc[32 + 8 + u],  misc[8 + u]);
      float zg = fmaf(x0, misc[32 + 12 + u], misc[12 + u]);
      float c = sigf(zi) * tanhf_fast(zg);
      c1s[u] = c;
      hv[u] = sigf(zo) * tanhf_fast(c);
    }
    h_write(g_h1[0], b, cta, hv);
  }
  for (int i = tid; i < 1024; i += NTHR) g_h2[1][cta * 1024 + i] = 0u;

  unsigned gen;
  asm volatile("ld.acquire.gpu.u32 %0, [%1];" : "=r"(gen) : "l"(&g_flags[cta]));
  grid_barrier(gen);

  const uint2* Bsm = reinterpret_cast<const uint2*>(smem + SM_B);

  for (int t = 0; t < TPn; ++t) {
    const bool pred = (t >= Tn - 1);

    const uint4* pH2 = reinterpret_cast<const uint4*>(g_h2[(t ^ 1) & 1]);
    const uint4* pH1 = reinterpret_cast<const uint4*>(g_h1[t & 1]);

    float z2a[2][2][4], z1a[2][2][4];   // [mt][nt][ci]
#pragma unroll
    for (int i = 0; i < 16; ++i) {
      reinterpret_cast<float*>(z2a)[i] = 0.f;
      reinterpret_cast<float*>(z1a)[i] = 0.f;
    }

    // chunk cc = (local q)*2 + ph ; ph: 0 = h2 hi (Wh2), 1 = h1 hi (Wx2+Wh1)
    auto loadA = [&](int cc, uint4* a) {
      int q = kp * 16 + (cc >> 1), ph = cc & 1;
      const uint4* g = (ph ? pH1 : pH2) + ((q * 2) * 16 + mpp * 2) * 32 + lane;
      a[0] = ldcg128(g);
      a[1] = ldcg128(g + 32);
    };

    uint2 Bq[6];
    auto loadBq = [&](int q) {
#pragma unroll
      for (int m = 0; m < 3; ++m)
#pragma unroll
        for (int nt = 0; nt < 2; ++nt)
          Bq[m * 2 + nt] = Bsm[BOFF2(m, q, nt, lane)];
    };

    auto compute = [&](int cc, const uint4* a) {
      if ((cc & 1) == 0) {
#pragma unroll
        for (int mt = 0; mt < 2; ++mt)
#pragma unroll
          for (int nt = 0; nt < 2; ++nt)
            mma16816(z2a[mt][nt], a[mt], Bq[nt].x, Bq[nt].y);
      } else {
#pragma unroll
        for (int mt = 0; mt < 2; ++mt)
#pragma unroll
          for (int nt = 0; nt < 2; ++nt) {
            mma16816(z2a[mt][nt], a[mt], Bq[2 + nt].x, Bq[2 + nt].y);
            mma16816(z1a[mt][nt], a[mt], Bq[4 + nt].x, Bq[4 + nt].y);
          }
      }
    };

    // prime 6-deep ring, then overlap o(t-1) reduce with in-flight LDGs
    uint4 ar[6][2];
#pragma unroll
    for (int i = 0; i < 6; ++i) loadA(i, ar[i]);

    if (t >= 1 && t <= Tn - 1 && warp < 2) {
      int ob = 2 * cta + warp;
      float4 v = __ldcg(reinterpret_cast<const float4*>(g_opart + ob * NCTA) + lane);
      float p = v.x + v.y + v.z + v.w;
#pragma unroll
      for (int off = 16; off; off >>= 1) p += __shfl_xor_sync(0xffffffffu, p, off);
      if (lane == 0) g_out[(t - 1) * 256 + ob] = p;
    }

    // 32 chunks (own K half), fully unrolled
#pragma unroll
    for (int cc = 0; cc < 32; ++cc) {
      if ((cc & 1) == 0) loadBq(kp * 16 + (cc >> 1));
      compute(cc, ar[cc % 6]);
      if (cc < 26) loadA(cc + 6, ar[cc % 6]);
    }

    // ---- K-reduce: kp1 -> slot, kp0 adds, kp0 writes zbuf ----
    {
      int tk = mpp * 32 + lane;
      float2* slot = reinterpret_cast<float2*>(smem + SM_SLOT);
      if (kp == 1) {
        const float* zf2 = reinterpret_cast<const float*>(z2a);
        const float* zf1 = reinterpret_cast<const float*>(z1a);
#pragma unroll
        for (int i = 0; i < 8; ++i)
          slot[i * 256 + tk] = make_float2(zf2[2 * i], zf2[2 * i + 1]);
#pragma unroll
        for (int i = 0; i < 8; ++i)
          slot[(8 + i) * 256 + tk] = make_float2(zf1[2 * i], zf1[2 * i + 1]);
      }
      __syncthreads();
      if (kp == 0) {
        float* zf2 = reinterpret_cast<float*>(z2a);
        float* zf1 = reinterpret_cast<float*>(z1a);
#pragma unroll
        for (int i = 0; i < 8; ++i) {
          float2 v = slot[i * 256 + tk];
          zf2[2 * i] += v.x; zf2[2 * i + 1] += v.y;
        }
#pragma unroll
        for (int i = 0; i < 8; ++i) {
          float2 v = slot[(8 + i) * 256 + tk];
          zf1[2 * i] += v.x; zf1[2 * i + 1] += v.y;
        }
        float* zb = reinterpret_cast<float*>(smem + SM_Z);
#pragma unroll
        for (int mt = 0; mt < 2; ++mt)
#pragma unroll
          for (int nt = 0; nt < 2; ++nt)
#pragma unroll
            for (int ci = 0; ci < 4; ++ci) {
              int b  = mpp * 32 + mt * 16 + (lane >> 2) + 8 * (ci >> 1);
              int gc = nt * 8 + (lane & 3) * 2 + (ci & 1);
              zb[gc * 257 + b]        = z2a[mt][nt][ci];
              zb[(16 + gc) * 257 + b] = z1a[mt][nt][ci];
            }
      }
    }
    __syncthreads();

    // ---- epilogue layer 2 -> h2(t), opart ----
    const float* zb = reinterpret_cast<const float*>(smem + SM_Z);
    if (tid < 256) {
      int b = tid;
      float hv[4], op = 0.f;
#pragma unroll
      for (int u = 0; u < 4; ++u) {
        float zi = zb[(u) * 257 + b]      + misc[16 + u];
        float zf = zb[(4 + u) * 257 + b]  + misc[16 + 4 + u];
        float zo = zb[(8 + u) * 257 + b]  + misc[16 + 8 + u];
        float zg = zb[(12 + u) * 257 + b] + misc[16 + 12 + u];
        float c = sigf(zf) * c2s[u] + sigf(zi) * tanhf_fast(zg);
        c2s[u] = c;
        hv[u] = sigf(zo) * tanhf_fast(c);
        op = fmaf(hv[u], misc[48 + u], op);
      }
      h_write(g_h2[t & 1], b, cta, hv);
      g_opart[b * NCTA + cta] = op;
    }

    // ---- next input ----
    float xnext = 0.f;
    if (!pred) {
      if (tid < 256) xnext = __ldg(&seq[tid * Tn + (t + 1)]);
    } else {
      grid_barrier(gen);
      if (warp < 2) {
        int ob = 2 * cta + warp;
        float4 v = __ldcg(reinterpret_cast<const float4*>(g_opart + ob * NCTA) + lane);
        float p = v.x + v.y + v.z + v.w;
#pragma unroll
        for (int off = 16; off; off >>= 1) p += __shfl_xor_sync(0xffffffffu, p, off);
        if (lane == 0) g_out[t * 256 + ob] = p;
      }
      grid_barrier(gen);
      if (tid < 256) xnext = __ldcg(&g_out[t * 256 + tid]) + bl0;
    }

    // ---- epilogue layer 1 -> h1(t+1) ----
    if (tid < 256) {
      int b = tid;
      float hv[4];
#pragma unroll
      for (int u = 0; u < 4; ++u) {
        float zi = fmaf(xnext, misc[32 + u],      zb[(16 + u) * 257 + b]      + misc[u]);
        float zf = fmaf(xnext, misc[32 + 4 + u],  zb[(16 + 4 + u) * 257 + b]  + misc[4 + u]);
        float zo = fmaf(xnext, misc[32 + 8 + u],  zb[(16 + 8 + u) * 257 + b]  + misc[8 + u]);
        float zg = fmaf(xnext, misc[32 + 12 + u], zb[(16 + 12 + u) * 257 + b] + misc[12 + u]);
        float c = sigf(zf) * c1s[u] + sigf(zi) * tanhf_fast(zg);
        c1s[u] = c;
        hv[u] = sigf(zo) * tanhf_fast(c);
      }
      h_write(g_h1[(t + 1) & 1], b, cta, hv);
    }
    grid_barrier(gen);
  }

  // out[b][tp] = o + bl
  for (int idx = cta * NTHR + tid; idx < TPn * 256; idx += NCTA * NTHR) {
    int b = idx / TPn, tp = idx - b * TPn;
    out[idx] = __ldcg(&g_out[tp * 256 + b]) + bl0;
  }
}

extern "C" void kernel_launch(void* const* d_in, const int* in_sizes, int n_in,
                              void* d_out, int out_size) {
  (void)in_sizes; (void)n_in; (void)out_size;
  const float* seq = (const float*)d_in[0];
  const float* Wx1 = (const float*)d_in[2];
  const float* bx1 = (const float*)d_in[3];
  const float* Wh1 = (const float*)d_in[4];
  const float* bh1 = (const float*)d_in[5];
  const float* Wx2 = (const float*)d_in[6];
  const float* bx2 = (const float*)d_in[7];
  const float* Wh2 = (const float*)d_in[8];
  const float* bh2 = (const float*)d_in[9];
  const float* Wl  = (const float*)d_in[10];
  const float* bl  = (const float*)d_in[11];

  cudaFuncSetAttribute(sine_rnn_kernel,
                       cudaFuncAttributeMaxDynamicSharedMemorySize, SM_TOTAL);
  sine_rnn_kernel<<<NCTA, NTHR, SM_TOTAL>>>(
      seq, Wx1, bx1, Wh1, bh1, Wx2, bx2, Wh2, bh2, Wl, bl, (float*)d_out);
}